// round 3
// baseline (speedup 1.0000x reference)
#include <cuda_runtime.h>
#include <cuda_bf16.h>

// Kuramoto–Sivashinsky explicit Euler, periodic BCs.
//   u_t = -c u u_x - alpha u_xx - beta u_xxxx,  dx=1, dt=0.01, NT=1000
// Restructured per-point update (dx=1 so inv_dx2=inv_dx4=1, inv_2dx=0.5):
//   u' = A2*(um2+up2) + A1*(um1+up1) + CN*u*(um1-up1) + A0*u
//   A2 = -dt*beta; A1 = dt*(4*beta - alpha); A0 = 1 + dt*(2*alpha - 6*beta); CN = 0.5*dt*c
//
// Mapping: 1 CTA per batch row (64 CTAs), 512 threads, 4 consecutive points per
// thread held in registers as two packed f32x2 values. Halo (2 points each side)
// exchanged through a double-buffered SMEM array -> exactly one __syncthreads()
// per time step. All arithmetic uses sm_103a packed f32x2 PTX (FFMA2 in SASS),
// halving fma-pipe pressure vs scalar fp32.

#define KS_NT   1000
#define KS_NB   64
#define KS_NX   2048
#define KS_TPB  512   // 4 points per thread

typedef unsigned long long u64;

__device__ __forceinline__ u64 pk2(float lo, float hi) {
    u64 r; asm("mov.b64 %0, {%1, %2};" : "=l"(r) : "f"(lo), "f"(hi)); return r;
}
__device__ __forceinline__ float lo2(u64 v) {
    float a, b; asm("mov.b64 {%0, %1}, %2;" : "=f"(a), "=f"(b) : "l"(v)); return a;
}
__device__ __forceinline__ float hi2(u64 v) {
    float a, b; asm("mov.b64 {%0, %1}, %2;" : "=f"(a), "=f"(b) : "l"(v)); return b;
}
__device__ __forceinline__ u64 fadd2(u64 a, u64 b) {
    u64 r; asm("add.rn.f32x2 %0, %1, %2;" : "=l"(r) : "l"(a), "l"(b)); return r;
}
__device__ __forceinline__ u64 fmul2(u64 a, u64 b) {
    u64 r; asm("mul.rn.f32x2 %0, %1, %2;" : "=l"(r) : "l"(a), "l"(b)); return r;
}
__device__ __forceinline__ u64 ffma2(u64 a, u64 b, u64 c) {
    u64 r; asm("fma.rn.f32x2 %0, %1, %2, %3;" : "=l"(r) : "l"(a), "l"(b), "l"(c)); return r;
}

__global__ void __launch_bounds__(KS_TPB, 1)
ks_kernel(const float* __restrict__ u0,
          const float* __restrict__ cptr,
          const float* __restrict__ aptr,
          const float* __restrict__ bptr,
          float* __restrict__ out)
{
    // double-buffered halo exchange: each thread publishes its 4 points (16B)
    __shared__ ulonglong2 sh[2][KS_TPB];

    const int tid = threadIdx.x;
    const int row = blockIdx.x;

    const float cc    = *cptr;
    const float alpha = *aptr;
    const float beta  = *bptr;
    const float DTf   = 0.01f;

    const float A2 = -DTf * beta;
    const float A1 =  DTf * (4.0f * beta - alpha);
    const float A0 =  1.0f + DTf * (2.0f * alpha - 6.0f * beta);
    const float CN =  0.5f * DTf * cc;

    const u64 A2p = pk2(A2, A2);
    const u64 A1p = pk2(A1, A1);
    const u64 A0p = pk2(A0, A0);
    const u64 CNp = pk2(CN, CN);
    const u64 N1p = pk2(-1.0f, -1.0f);

    const size_t base = (size_t)row * KS_NX + (size_t)(tid << 2);

    // load initial state (16B) and emit step 0 = u0
    float4 iv = *(const float4*)(u0 + base);
    *(float4*)(out + base) = iv;

    u64 v0 = pk2(iv.x, iv.y);   // points 0,1
    u64 v1 = pk2(iv.z, iv.w);   // points 2,3

    float* outp = out + (size_t)KS_NB * KS_NX + base;   // step 1 slot
    const size_t ostride = (size_t)KS_NB * KS_NX;

    const int lidx = (tid - 1) & (KS_TPB - 1);
    const int ridx = (tid + 1) & (KS_TPB - 1);

    #pragma unroll 1
    for (int step = 0; step < KS_NT; step += 2) {
        #pragma unroll
        for (int half = 0; half < 2; ++half) {
            ulonglong2* buf = sh[half];

            buf[tid] = make_ulonglong2(v0, v1);
            __syncthreads();
            const u64 hl = buf[lidx].y;   // left  neighbor's (u[-2], u[-1])
            const u64 hr = buf[ridx].x;   // right neighbor's (u[4],  u[5])

            // composed (shifted) pairs
            const u64 m01 = pk2(hi2(hl), lo2(v0));  // (u[-1], u0)
            const u64 c12 = pk2(hi2(v0), lo2(v1));  // (u1, u2)
            const u64 p34 = pk2(hi2(v1), lo2(hr));  // (u3, u4)

            // pair 0: points (0,1)  um2=hl  um1=m01  up1=c12  up2=v1
            u64 s1  = fadd2(c12, m01);
            u64 s2  = fadd2(v1, hl);
            u64 d   = ffma2(c12, N1p, m01);      // um1 - up1
            u64 pd  = fmul2(v0, d);
            u64 acc = ffma2(pd, CNp, fmul2(v0, A0p));
            acc     = ffma2(s1, A1p, acc);
            const u64 nv0 = ffma2(s2, A2p, acc);

            // pair 1: points (2,3)  um2=v0  um1=c12  up1=p34  up2=hr
            s1  = fadd2(p34, c12);
            s2  = fadd2(hr, v0);
            d   = ffma2(p34, N1p, c12);
            pd  = fmul2(v1, d);
            acc = ffma2(pd, CNp, fmul2(v1, A0p));
            acc = ffma2(s1, A1p, acc);
            const u64 nv1 = ffma2(s2, A2p, acc);

            v0 = nv0;
            v1 = nv1;

            *(ulonglong2*)outp = make_ulonglong2(v0, v1);  // 16B streaming store
            outp += ostride;
        }
    }
}

extern "C" void kernel_launch(void* const* d_in, const int* in_sizes, int n_in,
                              void* d_out, int out_size)
{
    (void)in_sizes; (void)n_in; (void)out_size;
    const float* u0    = (const float*)d_in[0];
    const float* c     = (const float*)d_in[1];
    const float* alpha = (const float*)d_in[2];
    const float* beta  = (const float*)d_in[3];
    ks_kernel<<<KS_NB, KS_TPB>>>(u0, c, alpha, beta, (float*)d_out);
}